// round 4
// baseline (speedup 1.0000x reference)
#include <cuda_runtime.h>
#include <cstdint>

// ---------------------------------------------------------------------------
// StableSpikingCoreFlow: T=64, B=128, D=N=2048, L=4, OUT=1024
//
// Identity: mean_t(gathered_t @ W^T) = (mean_t gathered_t) @ W^T; the next
// layer consumes mean_t(spikes) = count/64 (dyadic -> exact). Output = total
// spike counts at out_idx.
//
// Round 4: 1024 threads (32 warps/SM), split-K x8, cp.async double-buffered
// k-major tiles, fma.rn.f32x2 packed dual-FMA accumulation (even/odd k
// chains), chunked folding every 32 k + pairwise tree merge of 8 partials.
// ---------------------------------------------------------------------------

#define Bc   128
#define Dc   2048
#define Nc   2048
#define Tc   64
#define Lc   4
#define OUTc 1024

#define BM 32
#define BN 64
#define BK 16
#define NTHREADS 1024
#define NGROUPS 8
#define KSLICE (Dc / NGROUPS)   // 256
#define NKB (KSLICE / BK)       // 16

// smem tiles, k-major rows padded to 20 floats (80 B) -> conflict-free LDS.128
#define AROW 20
#define BROW 20
#define AS_SZ (BM * AROW)        // 640
#define BS_SZ (BN * BROW)        // 1280
#define TILE_SZ (AS_SZ + BS_SZ)  // 1920 floats per group per buffer
#define PS_OFF (2 * NGROUPS * TILE_SZ)             // 30720
#define SMEM_FLOATS (PS_OFF + NGROUPS * BM * BN)   // 47104
#define SMEM_BYTES (SMEM_FLOATS * 4)               // 188416

// scratch (no cudaMalloc allowed)
__device__ float g_G [Bc * Dc];
__device__ float g_R0[Bc * Nc];
__device__ float g_R1[Bc * Nc];

// ---------------------------------------------------------------------------
__device__ __forceinline__ void cp16(uint32_t dst, const float* src) {
    asm volatile("cp.async.cg.shared.global [%0], [%1], 16;\n"
                 :: "r"(dst), "l"(src));
}
#define CP_COMMIT() asm volatile("cp.async.commit_group;\n" ::: "memory")
#define CP_WAIT(n)  asm volatile("cp.async.wait_group %0;\n" :: "n"(n) : "memory")

__device__ __forceinline__ void ffma2(unsigned long long& c,
                                      unsigned long long a,
                                      unsigned long long b) {
    asm volatile("fma.rn.f32x2 %0, %1, %2, %0;\n" : "+l"(c) : "l"(a), "l"(b));
}
__device__ __forceinline__ void fadd2(unsigned long long& s,
                                      unsigned long long v) {
    asm volatile("add.rn.f32x2 %0, %0, %1;\n" : "+l"(s) : "l"(v));
}

__device__ __forceinline__ float tree8(float a, float b, float c, float d,
                                       float e, float f, float g, float h) {
    return __fadd_rn(__fadd_rn(__fadd_rn(a, b), __fadd_rn(c, d)),
                     __fadd_rn(__fadd_rn(e, f), __fadd_rn(g, h)));
}

// exact fp32 semantics of the reference spike scan
__device__ __forceinline__ float spike_rate(float a, float thr) {
    int c;
    if (a <= 0.f) {
        c = 0;                       // thr > 0: m never exceeds thr
    } else if (a > thr) {
        c = Tc;                      // spikes every step, exactly
    } else {
        float m = 0.f; c = 0;
        for (int t = 0; t < Tc; t++) {
            m += a;
            if (m > thr) { m -= thr; c++; }
        }
    }
    return (float)c * (1.0f / Tc);
}

// ---------------------------------------------------------------------------
__global__ void gather_kernel(const float* __restrict__ Rin,
                              const int*   __restrict__ axon,
                              float*       __restrict__ G)
{
    int idx = blockIdx.x * blockDim.x + threadIdx.x;
    if (idx >= Bc * Dc) return;
    int b = idx >> 11;
    int a = idx & 2047;
    G[idx] = Rin[(b << 11) + axon[a]];
}

// ---------------------------------------------------------------------------
// per-tile 4x4 (packed) outer product, k-major smem tiles
__device__ __forceinline__ void mma_tile(const float* __restrict__ As,
                                         const float* __restrict__ Bs,
                                         int mb, int nb,
                                         unsigned long long (&acc)[4][4])
{
#pragma unroll
    for (int c = 0; c < 4; c++) {            // 4 k-values per chunk (2 pairs)
        ulonglong2 a[4];
#pragma unroll
        for (int i = 0; i < 4; i++)
            a[i] = *reinterpret_cast<const ulonglong2*>(
                       As + (mb + 8 * i) * AROW + c * 4);
#pragma unroll
        for (int j = 0; j < 4; j++) {
            ulonglong2 b = *reinterpret_cast<const ulonglong2*>(
                               Bs + (nb + 4 * j) * BROW + c * 4);
#pragma unroll
            for (int i = 0; i < 4; i++) {
                ffma2(acc[i][j], a[i].x, b.x);   // k even/odd pair 0,1
                ffma2(acc[i][j], a[i].y, b.y);   // k even/odd pair 2,3
            }
        }
    }
}

// ---------------------------------------------------------------------------
__global__ __launch_bounds__(NTHREADS, 1)
void layer_kernel(const float* __restrict__ G,     // [B, D]
                  const float* __restrict__ W,     // [N, D] row-major
                  const float* __restrict__ thresholds,
                  int l,
                  float* __restrict__ Rout)        // [B, N] rates = c/64
{
    extern __shared__ float sm[];

    const int tid  = threadIdx.x;
    const int gid  = tid >> 7;      // split-K group 0..7
    const int gt   = tid & 127;
    const int warp = gt >> 5;
    const int lane = gt & 31;

    const int bm = blockIdx.y * BM;
    const int bn = blockIdx.x * BN;
    const int kbase = gid * KSLICE;

    float* As[2] = { sm + gid * TILE_SZ,
                     sm + (NGROUPS + gid) * TILE_SZ };
    float* Bs[2] = { As[0] + AS_SZ, As[1] + AS_SZ };
    float* Ps    = sm + PS_OFF;

    // cp.async load mapping (per group: A 32x16, B 64x16, 3 x 16B per thread)
    const int arow  = gt >> 2;
    const int ach   = (gt & 3) * 4;
    const int brow0 = gt >> 2;
    const int brow1 = (gt >> 2) + 32;

    const float* gA  = G + (size_t)(bm + arow)  * Dc + kbase + ach;
    const float* gB0 = W + (size_t)(bn + brow0) * Dc + kbase + ach;
    const float* gB1 = W + (size_t)(bn + brow1) * Dc + kbase + ach;

    uint32_t sA[2], sB0[2], sB1[2];
#pragma unroll
    for (int u = 0; u < 2; u++) {
        sA[u]  = (uint32_t)__cvta_generic_to_shared(As[u] + arow  * AROW + ach);
        sB0[u] = (uint32_t)__cvta_generic_to_shared(Bs[u] + brow0 * BROW + ach);
        sB1[u] = (uint32_t)__cvta_generic_to_shared(Bs[u] + brow1 * BROW + ach);
    }

#define ISSUE(t, buf) do { \
        cp16(sA[buf],  gA  + (t) * BK); \
        cp16(sB0[buf], gB0 + (t) * BK); \
        cp16(sB1[buf], gB1 + (t) * BK); \
        CP_COMMIT(); \
    } while (0)

    // compute mapping: m = mb + 8i, n = nb + 4j
    const int mb = lane >> 2;                 // 0..7
    const int nb = warp * 16 + (lane & 3);    // 0..51

    unsigned long long acc[4][4], ksum[4][4];
#pragma unroll
    for (int i = 0; i < 4; i++)
#pragma unroll
        for (int j = 0; j < 4; j++) { acc[i][j] = 0ull; ksum[i][j] = 0ull; }

    // prologue: 2 tiles in flight
    ISSUE(0, 0);
    ISSUE(1, 1);

    for (int kb2 = 0; kb2 < NKB; kb2 += 2) {
        // even tile -> buf0
        CP_WAIT(1);
        __syncthreads();
        mma_tile(As[0], Bs[0], mb, nb, acc);
        __syncthreads();
        if (kb2 + 2 < NKB) ISSUE(kb2 + 2, 0);

        // odd tile -> buf1
        if (kb2 + 2 < NKB) { CP_WAIT(1); } else { CP_WAIT(0); }
        __syncthreads();
        mma_tile(As[1], Bs[1], mb, nb, acc);

        // fold chunk (32 k) into running sum
#pragma unroll
        for (int i = 0; i < 4; i++)
#pragma unroll
            for (int j = 0; j < 4; j++) {
                fadd2(ksum[i][j], acc[i][j]);
                acc[i][j] = 0ull;
            }

        __syncthreads();
        if (kb2 + 3 < NKB) ISSUE(kb2 + 3, 1);
    }
#undef ISSUE

    // group partial: combine even/odd chains, store to smem
#pragma unroll
    for (int i = 0; i < 4; i++)
#pragma unroll
        for (int j = 0; j < 4; j++) {
            unsigned long long v = ksum[i][j];
            float lo = __uint_as_float((unsigned)v);
            float hi = __uint_as_float((unsigned)(v >> 32));
            Ps[gid * (BM * BN) + (mb + 8 * i) * BN + (nb + 4 * j)] =
                __fadd_rn(lo, hi);
        }
    __syncthreads();

    // merge 8 group partials (pairwise tree) + fused spike scan, 2 out/thread
    {
        const int idx = tid * 2;
        const int m = idx >> 6;
        const int n = idx & 63;
        float2 p0 = *(const float2*)&Ps[0 * (BM * BN) + idx];
        float2 p1 = *(const float2*)&Ps[1 * (BM * BN) + idx];
        float2 p2 = *(const float2*)&Ps[2 * (BM * BN) + idx];
        float2 p3 = *(const float2*)&Ps[3 * (BM * BN) + idx];
        float2 p4 = *(const float2*)&Ps[4 * (BM * BN) + idx];
        float2 p5 = *(const float2*)&Ps[5 * (BM * BN) + idx];
        float2 p6 = *(const float2*)&Ps[6 * (BM * BN) + idx];
        float2 p7 = *(const float2*)&Ps[7 * (BM * BN) + idx];

        float ax = tree8(p0.x, p1.x, p2.x, p3.x, p4.x, p5.x, p6.x, p7.x);
        float ay = tree8(p0.y, p1.y, p2.y, p3.y, p4.y, p5.y, p6.y, p7.y);

        const float thr = thresholds[l];
        float2 outv;
        outv.x = spike_rate(ax, thr);
        outv.y = spike_rate(ay, thr);
        *(float2*)&Rout[(bm + m) * Nc + bn + n] = outv;
    }
}

// ---------------------------------------------------------------------------
__global__ void out_kernel(const float* __restrict__ R,
                           const int*   __restrict__ out_idx,
                           float*       __restrict__ out)
{
    int idx = blockIdx.x * blockDim.x + threadIdx.x;
    if (idx >= Bc * OUTc) return;
    int b = idx >> 10;
    int o = idx & 1023;
    out[idx] = R[(b << 11) + out_idx[o]] * (float)Tc;  // rate*64 = count, exact
}

// ---------------------------------------------------------------------------
extern "C" void kernel_launch(void* const* d_in, const int* in_sizes, int n_in,
                              void* d_out, int out_size)
{
    const float* x       = (const float*)d_in[0];   // [B, D]
    const float* W       = (const float*)d_in[1];   // [L, N, D]
    const float* thr     = (const float*)d_in[2];   // [L]
    const int*   axon    = (const int*)  d_in[3];   // [L, D]
    const int*   out_idx = (const int*)  d_in[4];   // [OUT]
    (void)in_sizes; (void)n_in; (void)out_size;

    cudaFuncSetAttribute(layer_kernel,
                         cudaFuncAttributeMaxDynamicSharedMemorySize,
                         SMEM_BYTES);

    float *G, *R0, *R1;
    cudaGetSymbolAddress((void**)&G,  g_G);
    cudaGetSymbolAddress((void**)&R0, g_R0);
    cudaGetSymbolAddress((void**)&R1, g_R1);
    float* bufs[2] = { R0, R1 };

    dim3 ggrid((Bc * Dc + 255) / 256);
    dim3 lgrid(Nc / BN, Bc / BM);   // (32, 4) = 128 blocks

    const float* rin = x;
    for (int l = 0; l < Lc; l++) {
        gather_kernel<<<ggrid, 256>>>(rin, axon + l * Dc, G);
        layer_kernel <<<lgrid, NTHREADS, SMEM_BYTES>>>(
            G, W + (size_t)l * Nc * Dc, thr, l, bufs[l & 1]);
        rin = bufs[l & 1];
    }
    out_kernel<<<(Bc * OUTc + 255) / 256, 256>>>(rin, out_idx, (float*)d_out);
}

// round 5
// speedup vs baseline: 1.3941x; 1.3941x over previous
#include <cuda_runtime.h>
#include <cstdint>

// ---------------------------------------------------------------------------
// StableSpikingCoreFlow: T=64, B=128, D=N=2048, L=4, OUT=1024
//
// Identity: mean_t(gathered_t @ W^T) = (mean_t gathered_t) @ W^T; the next
// layer consumes mean_t(spikes) = count/64 (dyadic -> exact). Output = total
// spike counts at out_idx.
//
// Round 5: 512 threads, 8 warp-pair split-K groups (KSLICE=256), per-thread
// 4m x 8n register tile with fma.rn.f32x2 (even/odd-k chains, 32 packed
// accumulators = 64 regs), cp.async double-buffered BK=8 tiles, partials
// flushed to smem every 128 k (chain length 64 per f32x2 half), tree-16
// merge + fused spike scan.
// ---------------------------------------------------------------------------

#define Bc   128
#define Dc   2048
#define Nc   2048
#define Tc   64
#define Lc   4
#define OUTc 1024

#define BM 32
#define BN 64
#define BK 8
#define NTHREADS 512
#define NGROUPS 8               // one warp-pair per group
#define KSLICE (Dc / NGROUPS)   // 256
#define NKB (KSLICE / BK)       // 32 tiles per group

// smem tiles: rows hold BK=8 k-floats (32B), padded to 48B (12 floats) so
// cp.async 16B chunks stay aligned and LDS.128 row offsets mod 128 are all
// distinct (conflict-free).
#define ROWF 12
#define AS_SZ (BM * ROWF)        // 384 floats
#define BS_SZ (BN * ROWF)        // 768 floats
#define TILE_SZ (AS_SZ + BS_SZ)  // 1152 floats per group per buffer
#define PS_OFF (2 * NGROUPS * TILE_SZ)             // 18432 floats (72KB)
#define NPLANES 16                                  // 8 groups x 2 k-halves
#define SMEM_FLOATS (PS_OFF + NPLANES * BM * BN)    // 18432 + 32768 = 51200
#define SMEM_BYTES (SMEM_FLOATS * 4)                // 204800

// scratch (no cudaMalloc allowed)
__device__ float g_G [Bc * Dc];
__device__ float g_R0[Bc * Nc];
__device__ float g_R1[Bc * Nc];

// ---------------------------------------------------------------------------
__device__ __forceinline__ void cp16(uint32_t dst, const float* src) {
    asm volatile("cp.async.cg.shared.global [%0], [%1], 16;\n"
                 :: "r"(dst), "l"(src));
}
#define CP_COMMIT() asm volatile("cp.async.commit_group;\n" ::: "memory")
#define CP_WAIT(n)  asm volatile("cp.async.wait_group %0;\n" :: "n"(n) : "memory")

__device__ __forceinline__ void ffma2(unsigned long long& c,
                                      unsigned long long a,
                                      unsigned long long b) {
    asm volatile("fma.rn.f32x2 %0, %1, %2, %0;\n" : "+l"(c) : "l"(a), "l"(b));
}

__device__ __forceinline__ float pair_sum(unsigned long long v) {
    float lo = __uint_as_float((unsigned)v);
    float hi = __uint_as_float((unsigned)(v >> 32));
    return __fadd_rn(lo, hi);
}

// exact fp32 semantics of the reference spike scan
__device__ __forceinline__ float spike_rate(float a, float thr) {
    int c;
    if (a <= 0.f) {
        c = 0;                       // thr > 0: m never exceeds thr
    } else if (a > thr) {
        c = Tc;                      // spikes every step, exactly
    } else {
        float m = 0.f; c = 0;
        for (int t = 0; t < Tc; t++) {
            m += a;
            if (m > thr) { m -= thr; c++; }
        }
    }
    return (float)c * (1.0f / Tc);
}

// ---------------------------------------------------------------------------
__global__ void gather_kernel(const float* __restrict__ Rin,
                              const int*   __restrict__ axon,
                              float*       __restrict__ G)
{
    int idx = blockIdx.x * blockDim.x + threadIdx.x;
    if (idx >= Bc * Dc) return;
    int b = idx >> 11;
    int a = idx & 2047;
    G[idx] = Rin[(b << 11) + axon[a]];
}

// ---------------------------------------------------------------------------
__global__ __launch_bounds__(NTHREADS, 1)
void layer_kernel(const float* __restrict__ G,     // [B, D]
                  const float* __restrict__ W,     // [N, D] row-major
                  const float* __restrict__ thresholds,
                  int l,
                  float* __restrict__ Rout)        // [B, N] rates = c/64
{
    extern __shared__ float sm[];

    const int tid   = threadIdx.x;
    const int g     = tid >> 6;          // split-K group 0..7 (warp pair)
    const int gt2   = tid & 63;          // thread in group
    const int warpM = (tid >> 5) & 1;    // which 16-row m half
    const int lane  = tid & 31;
    const int mrow  = lane >> 3;         // 0..3
    const int ncol  = lane & 7;          // 0..7
    const int mbase = warpM * 16;

    const int bm = blockIdx.y * BM;
    const int bn = blockIdx.x * BN;
    const int kbase = g * KSLICE;

    float* As0 = sm + (0 * NGROUPS + g) * TILE_SZ;
    float* As1 = sm + (1 * NGROUPS + g) * TILE_SZ;
    float* Bs0 = As0 + AS_SZ;
    float* Bs1 = As1 + AS_SZ;
    float* Ps  = sm + PS_OFF;

    // cp.async mapping: A 64 chunks (32 rows x 2), B 128 chunks (64 rows x 2)
    const int am = gt2 >> 1;          // A row 0..31
    const int ac = gt2 & 1;           // A 16B chunk 0..1
    const int bn0 = gt2 >> 1;         // B row 0..31 (r=0)
    const int bn1 = (gt2 + 64) >> 1;  // B row 32..63 (r=1)

    const float* gA  = G + (size_t)(bm + am)  * Dc + kbase + ac * 4;
    const float* gB0 = W + (size_t)(bn + bn0) * Dc + kbase + ac * 4;
    const float* gB1 = W + (size_t)(bn + bn1) * Dc + kbase + ac * 4;

    const uint32_t sA0  = (uint32_t)__cvta_generic_to_shared(As0 + am  * ROWF + ac * 4);
    const uint32_t sA1  = (uint32_t)__cvta_generic_to_shared(As1 + am  * ROWF + ac * 4);
    const uint32_t sB00 = (uint32_t)__cvta_generic_to_shared(Bs0 + bn0 * ROWF + ac * 4);
    const uint32_t sB01 = (uint32_t)__cvta_generic_to_shared(Bs1 + bn0 * ROWF + ac * 4);
    const uint32_t sB10 = (uint32_t)__cvta_generic_to_shared(Bs0 + bn1 * ROWF + ac * 4);
    const uint32_t sB11 = (uint32_t)__cvta_generic_to_shared(Bs1 + bn1 * ROWF + ac * 4);

#define ISSUE(t, buf) do { \
        if (buf) { \
            cp16(sA1,  gA  + (t) * BK); \
            cp16(sB01, gB0 + (t) * BK); \
            cp16(sB11, gB1 + (t) * BK); \
        } else { \
            cp16(sA0,  gA  + (t) * BK); \
            cp16(sB00, gB0 + (t) * BK); \
            cp16(sB10, gB1 + (t) * BK); \
        } \
        CP_COMMIT(); \
    } while (0)

    // 32 packed accumulators: acc[i][j] = f32x2 (even-k chain, odd-k chain)
    // for output (m = mbase + mrow + 4i, n = ncol + 8j)
    unsigned long long acc[4][8];
#pragma unroll
    for (int i = 0; i < 4; i++)
#pragma unroll
        for (int j = 0; j < 8; j++) acc[i][j] = 0ull;

    ISSUE(0, 0);
    ISSUE(1, 1);

    for (int t = 0; t < NKB; t++) {
        if (t == NKB - 1) { CP_WAIT(0); } else { CP_WAIT(1); }
        __syncthreads();

        const float* As = (t & 1) ? As1 : Bs1 - BS_SZ - AS_SZ + AS_SZ; // silence
        As = (t & 1) ? As1 : As0;
        const float* Bs = (t & 1) ? Bs1 : Bs0;

        // 8 k-values = 2 x (LDS.128 = 2 f32x2 chunks)
#pragma unroll
        for (int h = 0; h < 2; h++) {
            ulonglong2 a[4];
#pragma unroll
            for (int i = 0; i < 4; i++)
                a[i] = *reinterpret_cast<const ulonglong2*>(
                           As + (mbase + mrow + 4 * i) * ROWF + h * 4);
#pragma unroll
            for (int j = 0; j < 8; j++) {
                ulonglong2 b = *reinterpret_cast<const ulonglong2*>(
                                   Bs + (ncol + 8 * j) * ROWF + h * 4);
#pragma unroll
                for (int i = 0; i < 4; i++) {
                    ffma2(acc[i][j], a[i].x, b.x);
                    ffma2(acc[i][j], a[i].y, b.y);
                }
            }
        }
        __syncthreads();
        if (t + 2 < NKB) ISSUE(t + 2, t & 1);

        // flush first k-half (128 k -> 64-term chains) to partial plane g
        if (t == NKB / 2 - 1) {
#pragma unroll
            for (int i = 0; i < 4; i++)
#pragma unroll
                for (int j = 0; j < 8; j++) {
                    Ps[g * (BM * BN)
                       + (mbase + mrow + 4 * i) * BN + (ncol + 8 * j)] =
                        pair_sum(acc[i][j]);
                    acc[i][j] = 0ull;
                }
        }
    }
#undef ISSUE

    // flush second k-half to plane 8+g
#pragma unroll
    for (int i = 0; i < 4; i++)
#pragma unroll
        for (int j = 0; j < 8; j++)
            Ps[(NGROUPS + g) * (BM * BN)
               + (mbase + mrow + 4 * i) * BN + (ncol + 8 * j)] =
                pair_sum(acc[i][j]);
    __syncthreads();

    // tree-16 merge + fused spike scan, 4 outputs per thread
    {
        const int idx = tid * 4;
        const int m = idx >> 6;
        const int n = idx & 63;

        float4 v[NPLANES];
#pragma unroll
        for (int p = 0; p < NPLANES; p++)
            v[p] = *(const float4*)&Ps[p * (BM * BN) + idx];

        float av[4];
#pragma unroll
        for (int q = 0; q < 4; q++) {
            float e[NPLANES];
#pragma unroll
            for (int p = 0; p < NPLANES; p++)
                e[p] = (q == 0) ? v[p].x : (q == 1) ? v[p].y
                     : (q == 2) ? v[p].z : v[p].w;
            // fixed-order pairwise tree
#pragma unroll
            for (int s = 1; s < NPLANES; s <<= 1)
#pragma unroll
                for (int p = 0; p < NPLANES; p += 2 * s)
                    e[p] = __fadd_rn(e[p], e[p + s]);
            av[q] = e[0];
        }

        const float thr = thresholds[l];
        float4 outv;
        outv.x = spike_rate(av[0], thr);
        outv.y = spike_rate(av[1], thr);
        outv.z = spike_rate(av[2], thr);
        outv.w = spike_rate(av[3], thr);
        *(float4*)&Rout[(bm + m) * Nc + bn + n] = outv;
    }
}

// ---------------------------------------------------------------------------
__global__ void out_kernel(const float* __restrict__ R,
                           const int*   __restrict__ out_idx,
                           float*       __restrict__ out)
{
    int idx = blockIdx.x * blockDim.x + threadIdx.x;
    if (idx >= Bc * OUTc) return;
    int b = idx >> 10;
    int o = idx & 1023;
    out[idx] = R[(b << 11) + out_idx[o]] * (float)Tc;  // rate*64 = count, exact
}

// ---------------------------------------------------------------------------
extern "C" void kernel_launch(void* const* d_in, const int* in_sizes, int n_in,
                              void* d_out, int out_size)
{
    const float* x       = (const float*)d_in[0];   // [B, D]
    const float* W       = (const float*)d_in[1];   // [L, N, D]
    const float* thr     = (const float*)d_in[2];   // [L]
    const int*   axon    = (const int*)  d_in[3];   // [L, D]
    const int*   out_idx = (const int*)  d_in[4];   // [OUT]
    (void)in_sizes; (void)n_in; (void)out_size;

    cudaFuncSetAttribute(layer_kernel,
                         cudaFuncAttributeMaxDynamicSharedMemorySize,
                         SMEM_BYTES);

    float *G, *R0, *R1;
    cudaGetSymbolAddress((void**)&G,  g_G);
    cudaGetSymbolAddress((void**)&R0, g_R0);
    cudaGetSymbolAddress((void**)&R1, g_R1);
    float* bufs[2] = { R0, R1 };

    dim3 ggrid((Bc * Dc + 255) / 256);
    dim3 lgrid(Nc / BN, Bc / BM);   // (32, 4) = 128 blocks

    const float* rin = x;
    for (int l = 0; l < Lc; l++) {
        gather_kernel<<<ggrid, 256>>>(rin, axon + l * Dc, G);
        layer_kernel <<<lgrid, NTHREADS, SMEM_BYTES>>>(
            G, W + (size_t)l * Nc * Dc, thr, l, bufs[l & 1]);
        rin = bufs[l & 1];
    }
    out_kernel<<<(Bc * OUTc + 255) / 256, 256>>>(rin, out_idx, (float*)d_out);
}